// round 9
// baseline (speedup 1.0000x reference)
#include <cuda_runtime.h>
#include <math.h>
#include <float.h>

#define EE       64
#define TOPK_    8
#define BM       128
#define BK       32
#define NTHREADS 256

// Eigen gebp panel split on Grace (L1d=64KB, mr=12, nr=4): kc = 1016
#define SPLIT_CH 31        // 1016 = 31*32 + 24
#define SPLIT_KO 24

// packed fp32x2 ops (two IEEE fp32 lanes; identical rounding to scalar FFMA/FADD)
#define FMA2(d, a, b) asm("fma.rn.f32x2 %0, %1, %2, %0;" : "+l"(d) : "l"(a), "l"(b))
#define ADD2(d, a)    asm("add.rn.f32x2 %0, %0, %1;"     : "+l"(d) : "l"(a))

// Correctly-rounded-class fp32 sigmoid via float-float arithmetic (~2^-40 internal,
// one final rounding) — agrees with a glibc-class (correctly-rounded) exp reference.
__device__ __forceinline__ float sigmoid_cr(float x)
{
    float z = -x;
    z = fminf(fmaxf(z, -80.0f), 80.0f);
    const float n = rintf(z * 1.4426950408889634f);
    float r = fmaf(-n, 0.693145751953125f, z);       // ln2_hi (exact product bits)
    r = fmaf(-n, 1.4286068203e-06f, r);              // ln2_lo
    const float r2 = r * r;
    float p = 2.7557319e-6f;
    p = fmaf(p, r, 2.4801587e-5f);
    p = fmaf(p, r, 1.9841270e-4f);
    p = fmaf(p, r, 1.3888889e-3f);
    p = fmaf(p, r, 8.3333333e-3f);
    p = fmaf(p, r, 4.1666667e-2f);
    p = fmaf(p, r, 1.6666667e-1f);
    p = fmaf(p, r, 0.5f);
    const float q = r2 * p;                          // e^r - 1 - r (small)
    const float s1 = 1.0f + r;
    const float e1 = (1.0f - s1) + r;
    const float s2 = s1 + q;
    const float e2 = (s1 - s2) + q;
    const float elo = e1 + e2;
    const float sc = __int_as_float(((int)n + 127) << 23);
    const float Eh = s2 * sc;
    const float El = elo * sc;
    const float th = 1.0f + Eh;
    const float ap = th - Eh;
    const float bp = th - ap;
    const float tl = ((1.0f - ap) + (Eh - bp)) + El;
    const float y0 = __fdiv_rn(1.0f, th);
    float rr = fmaf(-y0, th, 1.0f);
    rr = fmaf(-y0, tl, rr);
    return fmaf(y0, rr, y0);
}

struct TileSm {
    float  xs[BK][BM];   // [k][token], token index XOR-swizzled by ((k>>2)&3)*8
    float2 ws[BK][EE];   // [k][expert], duplicated (w,w); expert XOR-swizzled by ((k>>2)&3)*4
};

union GateSm {
    TileSm t;                  // 32 KB
    float  sc[BM][EE + 2];     // 33.8 KB (sigmoid scores), aliases tiles after GEMM
};

__global__ __launch_bounds__(NTHREADS, 1)
void gate_kernel(const float* __restrict__ x, const float* __restrict__ wgt,
                 const float* __restrict__ bias, float* __restrict__ out,
                 int N, int D)
{
    __shared__ GateSm sm;
    __shared__ float sbias[EE];

    const int tid  = threadIdx.x;
    const int tx   = tid & 15;   // expert group: experts {tx, tx+16, tx+32, tx+48}
    const int ty   = tid >> 4;   // token group: tokens ty*8 .. ty*8+7
    const int row0 = blockIdx.x * BM;

    if (tid < EE) sbias[tid] = bias[tid];

    // global-load index precompute
    int xr[4], xkq[4];
#pragma unroll
    for (int q = 0; q < 4; q++) { int id = tid + NTHREADS * q; xr[q] = id >> 3; xkq[q] = id & 7; }
    int we[2], wkq[2];
#pragma unroll
    for (int q = 0; q < 2; q++) { int id = tid + NTHREADS * q; we[q] = id >> 3; wkq[q] = id & 7; }

    // Eigen-gebp-replica accumulation: two sequential ascending-k chains,
    // panel A = k in [0,1016), panel B = k in [1016,2048); logit = A + B.
    // acc = live chain, accS = banked panel-A result.
    unsigned long long acc[4][4], accS[4][4];
#pragma unroll
    for (int p = 0; p < 4; p++)
#pragma unroll
        for (int j = 0; j < 4; j++) { acc[p][j] = 0ull; accS[p][j] = 0ull; }

    const float* xblk = x + (size_t)row0 * D;

    // prefetch chunk 0 into registers
    float4 rx[4], rw[2];
#pragma unroll
    for (int q = 0; q < 4; q++)
        rx[q] = *(const float4*)(xblk + (size_t)xr[q] * D + xkq[q] * 4);
#pragma unroll
    for (int q = 0; q < 2; q++)
        rw[q] = *(const float4*)(wgt + (size_t)we[q] * D + wkq[q] * 4);

    const int nch = D / BK;
    for (int ch = 0; ch < nch; ch++) {
        __syncthreads();   // previous chunk's consumers done

        // store prefetched regs -> smem (swizzled, conflict-free)
#pragma unroll
        for (int q = 0; q < 4; q++) {
            const int kq  = xkq[q];
            const int col = xr[q] ^ ((kq & 3) * 8);
            sm.t.xs[kq * 4 + 0][col] = rx[q].x;
            sm.t.xs[kq * 4 + 1][col] = rx[q].y;
            sm.t.xs[kq * 4 + 2][col] = rx[q].z;
            sm.t.xs[kq * 4 + 3][col] = rx[q].w;
        }
#pragma unroll
        for (int q = 0; q < 2; q++) {
            const int kq  = wkq[q];
            const int col = we[q] ^ ((kq & 3) * 4);
            sm.t.ws[kq * 4 + 0][col] = make_float2(rw[q].x, rw[q].x);
            sm.t.ws[kq * 4 + 1][col] = make_float2(rw[q].y, rw[q].y);
            sm.t.ws[kq * 4 + 2][col] = make_float2(rw[q].z, rw[q].z);
            sm.t.ws[kq * 4 + 3][col] = make_float2(rw[q].w, rw[q].w);
        }
        __syncthreads();   // tiles ready

        // issue next chunk's global loads (overlap with compute)
        if (ch + 1 < nch) {
            const int kc = (ch + 1) * BK;
#pragma unroll
            for (int q = 0; q < 4; q++)
                rx[q] = *(const float4*)(xblk + (size_t)xr[q] * D + kc + xkq[q] * 4);
#pragma unroll
            for (int q = 0; q < 2; q++)
                rw[q] = *(const float4*)(wgt + (size_t)we[q] * D + kc + wkq[q] * 4);
        }

        // compute: 32 k-steps x 16 fma.f32x2 each, k strictly ascending.
        // At global k == 1016 (ch 31, step 24): bank panel A, restart chain.
#pragma unroll
        for (int k = 0; k < BK; k++) {
            if (k == SPLIT_KO && ch == SPLIT_CH) {
#pragma unroll
                for (int p = 0; p < 4; p++)
#pragma unroll
                    for (int j = 0; j < 4; j++) { accS[p][j] = acc[p][j]; acc[p][j] = 0ull; }
            }
            const int sxz = ((k >> 2) & 3) * 8;
            const int swz = ((k >> 2) & 3) * 4;
            const int tb  = (ty * 8) ^ sxz;
            const int eb  = tx ^ swz;
            unsigned long long xv[4], wv[4];
#pragma unroll
            for (int p = 0; p < 4; p++)
                xv[p] = *(const unsigned long long*)&sm.t.xs[k][tb + 2 * p];
#pragma unroll
            for (int j = 0; j < 4; j++)
                wv[j] = *(const unsigned long long*)&sm.t.ws[k][eb + 16 * j];
#pragma unroll
            for (int j = 0; j < 4; j++)
#pragma unroll
                for (int p = 0; p < 4; p++)
                    FMA2(acc[p][j], xv[p], wv[j]);
        }
    }

    // logit = panel A + panel B (single packed FADD, Eigen C += panel order)
#pragma unroll
    for (int p = 0; p < 4; p++)
#pragma unroll
        for (int j = 0; j < 4; j++)
            ADD2(accS[p][j], acc[p][j]);

    __syncthreads();   // all compute done before aliasing tiles with scores

    // correctly-rounded sigmoid -> scores in smem
#pragma unroll
    for (int p = 0; p < 4; p++) {
#pragma unroll
        for (int j = 0; j < 4; j++) {
            const unsigned long long a = accS[p][j];
            const float lo = __uint_as_float((unsigned)a);
            const float hi = __uint_as_float((unsigned)(a >> 32));
            const int e  = tx + 16 * j;
            const int t0 = ty * 8 + 2 * p;
            sm.sc[t0][e]     = sigmoid_cr(lo);
            sm.sc[t0 + 1][e] = sigmoid_cr(hi);
        }
    }
    __syncthreads();

    // top-8 per row: one warp per row, iterative warp-argmax (tie -> smaller index)
    const int lane = tid & 31;
    const int wid  = tid >> 5;
    float* outw = out;
    float* outi = out + (size_t)N * TOPK_;

    for (int rr = wid; rr < BM; rr += 8) {
        const float s0 = sm.sc[rr][lane];
        const float s1 = sm.sc[rr][lane + 32];
        float r0 = __fadd_rn(s0, sbias[lane]);
        float r1 = __fadd_rn(s1, sbias[lane + 32]);

        float wsel[TOPK_];
        int   isel[TOPK_];
        float sum = 0.0f;

#pragma unroll
        for (int t = 0; t < TOPK_; t++) {
            float v; int i;
            if (r1 > r0) { v = r1; i = lane + 32; } else { v = r0; i = lane; }
#pragma unroll
            for (int off = 16; off > 0; off >>= 1) {
                const float vo = __shfl_down_sync(0xffffffffu, v, off);
                const int   io = __shfl_down_sync(0xffffffffu, i, off);
                if (vo > v || (vo == v && io < i)) { v = vo; i = io; }
            }
            i = __shfl_sync(0xffffffffu, i, 0);
            if (i == lane)      r0 = -FLT_MAX;
            if (i == lane + 32) r1 = -FLT_MAX;
            const float orig = sm.sc[rr][i];        // original (un-biased) sigmoid score
            isel[t] = i;
            wsel[t] = orig;
            sum = __fadd_rn(sum, orig);             // sequential last-axis sum like reference
        }

        const float denom = __fadd_rn(sum, 1e-8f);  // (w / (sum+1e-8)) * 2.5, ref op order
        const int grow = row0 + rr;
#pragma unroll
        for (int t = 0; t < TOPK_; t++) {
            if (lane == t) {
                outw[(size_t)grow * TOPK_ + t] = __fmul_rn(__fdiv_rn(wsel[t], denom), 2.5f);
                outi[(size_t)grow * TOPK_ + t] = (float)isel[t];
            }
        }
    }
}

extern "C" void kernel_launch(void* const* d_in, const int* in_sizes, int n_in,
                              void* d_out, int out_size)
{
    const float* x = (const float*)d_in[0];
    const float* w = (const float*)d_in[1];
    const float* b = (const float*)d_in[2];

    const int E = in_sizes[2];          // 64
    const int D = in_sizes[1] / E;      // 2048
    const int N = in_sizes[0] / D;      // 16384
    (void)n_in; (void)out_size; (void)E;

    dim3 grid(N / BM);
    gate_kernel<<<grid, NTHREADS>>>(x, w, b, (float*)d_out, N, D);
}